// round 15
// baseline (speedup 1.0000x reference)
#include <cuda_runtime.h>
#include <cuda_fp16.h>
#include <cstdint>
#include <math.h>

#define SEQ 4096
#define DIM 1024

// ---------------- static device scratch (no allocation APIs) ----------------
__device__ __half g_Qh [SEQ * DIM];
__device__ __half g_Kh [SEQ * DIM];
__device__ __half g_VTh[SEQ * DIM];               // V transposed: [DIM][SEQ]
__device__ __half g_P  [(size_t)SEQ * SEQ];       // scores -> probs (fp16, in-place)
__device__ __half g_Xh [SEQ * DIM];               // fp16-rounded X
__device__ __half g_Wh [3 * DIM * DIM];           // fp16-rounded Wq,Wk,Wv

// ---------------- helpers ----------------
__device__ __forceinline__ uint32_t smem_u32(const void* p) {
    uint32_t a;
    asm("{ .reg .u64 t; cvta.to.shared.u64 t, %1; cvt.u32.u64 %0, t; }" : "=r"(a) : "l"(p));
    return a;
}
#define CP_COMMIT() asm volatile("cp.async.commit_group;" ::: "memory")
#define CP_WAIT(n)  asm volatile("cp.async.wait_group %0;" :: "n"(n) : "memory")

__device__ __forceinline__ void mma_f16(float* d, const uint32_t* a, const uint32_t* b) {
    asm volatile(
        "mma.sync.aligned.m16n8k16.row.col.f32.f16.f16.f32 "
        "{%0,%1,%2,%3}, {%4,%5,%6,%7}, {%8,%9}, {%0,%1,%2,%3};"
        : "+f"(d[0]), "+f"(d[1]), "+f"(d[2]), "+f"(d[3])
        : "r"(a[0]), "r"(a[1]), "r"(a[2]), "r"(a[3]), "r"(b[0]), "r"(b[1]));
}

#define LDSM_X4(r0, r1, r2, r3, addr) \
    asm volatile("ldmatrix.sync.aligned.m8n8.x4.shared.b16 {%0,%1,%2,%3}, [%4];" \
                 : "=r"(r0), "=r"(r1), "=r"(r2), "=r"(r3) : "r"(addr))

// ---------------- tile geometry (proven config — FROZEN) ----------------
// Block 128x128, BK=64 halves. 8 warps (2m x 4n), warp tile 64x32. 2 CTAs/SM.
static constexpr int BM           = 128;
static constexpr int BN           = 128;
static constexpr int STAGES       = 3;
static constexpr int STRIDE_H     = 72;                     // halves per smem row
static constexpr int STAGE_HALVES = (BM + BN) * STRIDE_H;   // 18432
static constexpr int STAGE_BYTES  = STAGE_HALVES * 2;       // 36864
static constexpr int SMEM_TOTAL   = STAGES * STAGE_BYTES;   // 110592

// ---------------------------------------------------------------------------
// NT GEMM: C[M,N] = alpha * A[M,K] * B[N,K]^T (+ bias), fp16 mma, fp32 accum.
// ldmatrix fragment loads. Grid: (N/BN, M/BM), 256 threads, 2 CTAs/SM.
// ---------------------------------------------------------------------------
template <bool HAS_BIAS, bool BIAS_ROW, bool STORE_HALF>
__global__ __launch_bounds__(256, 2)
void mma_gemm_h(const __half* __restrict__ A, const __half* __restrict__ B,
                const float* __restrict__ bias, void* __restrict__ Cv,
                int Kdim, int ldc, float alpha)
{
    extern __shared__ __half sm[];
    const int tid  = threadIdx.x;
    const int lane = tid & 31;
    const int wid  = tid >> 5;
    const int wm   = wid & 1;          // warp m: 0..1 (64 rows each)
    const int wn   = wid >> 1;         // warp n: 0..3 (32 cols each)
    const int lm   = lane >> 2;        // 0..7
    const int lc   = lane & 3;         // 0..3
    const int by   = blockIdx.y * BM;
    const int bx   = blockIdx.x * BN;

    const uint32_t sbase = smem_u32(sm);
    const __half* Abase = A + (size_t)by * Kdim;
    const __half* Bbase = B + (size_t)bx * Kdim;

    const uint32_t aOff = (uint32_t)(((wm * 64 + (lane & 15)) * STRIDE_H
                                      + (lane >> 4) * 8) * 2);
    const uint32_t bOff = (uint32_t)(((BM + wn * 32 + ((lane >> 4) & 1) * 8 + (lane & 7)) * STRIDE_H
                                      + ((lane >> 3) & 1) * 8) * 2);

    float acc[4][4][4];                // 4 mt x 4 nt x 4 = 64 regs
#pragma unroll
    for (int mt = 0; mt < 4; mt++)
#pragma unroll
        for (int nt = 0; nt < 4; nt++)
#pragma unroll
            for (int q = 0; q < 4; q++) acc[mt][nt][q] = 0.0f;

    const int NK = Kdim >> 6;          // K chunks of 64 halves

    const int ldRow = tid >> 3;        // 0..31
    const int ldC16 = tid & 7;         // 0..7

#define LOAD_STAGE(chunk, stg) do {                                              \
    const int _k0 = (chunk) * 64;                                                \
    const uint32_t _s = sbase + (stg) * STAGE_BYTES;                             \
    _Pragma("unroll")                                                            \
    for (int _i = 0; _i < 4; _i++) {                                             \
        const int _row = _i * 32 + ldRow;                                        \
        const uint32_t _dst = _s + (uint32_t)(_row * STRIDE_H + ldC16 * 8) * 2;  \
        const __half* _g = Abase + (size_t)_row * Kdim + _k0 + ldC16 * 8;        \
        asm volatile("cp.async.cg.shared.global [%0], [%1], 16;"                 \
                     :: "r"(_dst), "l"(_g) : "memory");                          \
    }                                                                            \
    _Pragma("unroll")                                                            \
    for (int _i = 0; _i < 4; _i++) {                                             \
        const int _row = _i * 32 + ldRow;                                        \
        const uint32_t _dst = _s + (uint32_t)((BM + _row) * STRIDE_H + ldC16 * 8) * 2; \
        const __half* _g = Bbase + (size_t)_row * Kdim + _k0 + ldC16 * 8;        \
        asm volatile("cp.async.cg.shared.global [%0], [%1], 16;"                 \
                     :: "r"(_dst), "l"(_g) : "memory");                          \
    }                                                                            \
} while (0)

#pragma unroll
    for (int s = 0; s < STAGES - 1; s++) {
        if (s < NK) LOAD_STAGE(s, s);
        CP_COMMIT();
    }

    for (int c = 0; c < NK; c++) {
        CP_WAIT(STAGES - 2);
        __syncthreads();               // chunk c resident; stage (c-1)%S free

        const uint32_t sstage = sbase + (c % STAGES) * STAGE_BYTES;
        const uint32_t aAddr = sstage + aOff;
        const uint32_t bAddr = sstage + bOff;

#pragma unroll
        for (int ks = 0; ks < 4; ks++) {       // 4 x k16 slices
            uint32_t afr[4][4], bfr[4][2];
#pragma unroll
            for (int mt = 0; mt < 4; mt++)
                LDSM_X4(afr[mt][0], afr[mt][1], afr[mt][2], afr[mt][3],
                        aAddr + (uint32_t)(mt * 16 * STRIDE_H * 2 + ks * 32));
#pragma unroll
            for (int nt2 = 0; nt2 < 2; nt2++)
                LDSM_X4(bfr[2 * nt2][0], bfr[2 * nt2][1],
                        bfr[2 * nt2 + 1][0], bfr[2 * nt2 + 1][1],
                        bAddr + (uint32_t)(nt2 * 16 * STRIDE_H * 2 + ks * 32));
#pragma unroll
            for (int mt = 0; mt < 4; mt++)
#pragma unroll
                for (int nt = 0; nt < 4; nt++)
                    mma_f16(acc[mt][nt], afr[mt], bfr[nt]);
        }

        const int nc = c + STAGES - 1;
        if (nc < NK) LOAD_STAGE(nc, nc % STAGES);
        CP_COMMIT();
    }
#undef LOAD_STAGE

    // ---- epilogue ----
#pragma unroll
    for (int mt = 0; mt < 4; mt++) {
        const int row0 = by + wm * 64 + mt * 16 + lm;   // and row0+8
        float brow0 = 0.0f, brow1 = 0.0f;
        if (HAS_BIAS && BIAS_ROW) { brow0 = bias[row0]; brow1 = bias[row0 + 8]; }
#pragma unroll
        for (int nt = 0; nt < 4; nt++) {
            const int col = bx + wn * 32 + nt * 8 + lc * 2;
            float v0 = acc[mt][nt][0] * alpha;
            float v1 = acc[mt][nt][1] * alpha;
            float v2 = acc[mt][nt][2] * alpha;
            float v3 = acc[mt][nt][3] * alpha;
            if (HAS_BIAS) {
                if (BIAS_ROW) { v0 += brow0; v1 += brow0; v2 += brow1; v3 += brow1; }
                else {
                    const float bc0 = bias[col], bc1 = bias[col + 1];
                    v0 += bc0; v1 += bc1; v2 += bc0; v3 += bc1;
                }
            }
            if (STORE_HALF) {
                __half* C = (__half*)Cv;
                *(__half2*)(C + (size_t)row0 * ldc + col)       = __floats2half2_rn(v0, v1);
                *(__half2*)(C + (size_t)(row0 + 8) * ldc + col) = __floats2half2_rn(v2, v3);
            } else {
                float* C = (float*)Cv;
                *(float2*)(C + (size_t)row0 * ldc + col)       = make_float2(v0, v1);
                *(float2*)(C + (size_t)(row0 + 8) * ldc + col) = make_float2(v2, v3);
            }
        }
    }
}

// ---------------------------------------------------------------------------
// Single fused fp32 -> fp16 pre-pass over X, Wq, Wk, Wv (one launch).
// ---------------------------------------------------------------------------
__global__ void f2h_all(const float* __restrict__ X,
                        const float* __restrict__ Wq,
                        const float* __restrict__ Wk,
                        const float* __restrict__ Wv,
                        __half* __restrict__ Xh, __half* __restrict__ Wh)
{
    const int NX = SEQ * DIM;
    const int NW = DIM * DIM;
    int i = (blockIdx.x * blockDim.x + threadIdx.x) * 4;

    const float* src;
    __half* dst;
    int off;
    if (i < NX)               { src = X;  dst = Xh;          off = i; }
    else if (i < NX + NW)     { src = Wq; dst = Wh;          off = i - NX; }
    else if (i < NX + 2 * NW) { src = Wk; dst = Wh + NW;     off = i - NX - NW; }
    else                      { src = Wv; dst = Wh + 2 * NW; off = i - NX - 2 * NW; }

    float4 v = *(const float4*)(src + off);
    __half2 h0 = __floats2half2_rn(v.x, v.y);
    __half2 h1 = __floats2half2_rn(v.z, v.w);
    uint2 u;
    u.x = *(uint32_t*)&h0;
    u.y = *(uint32_t*)&h1;
    *(uint2*)(dst + off) = u;
}

// ---------------------------------------------------------------------------
// In-place row softmax on fp16 scores (4096-wide rows, one block per row).
// ---------------------------------------------------------------------------
__global__ void softmax4096h(__half* __restrict__ P) {
    const int row = blockIdx.x;
    uint4* p = (uint4*)(P + (size_t)row * SEQ);   // 8 halves per uint4
    const int t = threadIdx.x;

    uint4 u[2];
    float v[2][8];
    float mx = -1e30f;
#pragma unroll
    for (int k = 0; k < 2; k++) {
        u[k] = p[t + 256 * k];
        const uint32_t* w = (const uint32_t*)&u[k];
#pragma unroll
        for (int j = 0; j < 4; j++) {
            float2 f = __half22float2(*(const __half2*)&w[j]);
            v[k][2 * j]     = f.x;
            v[k][2 * j + 1] = f.y;
            mx = fmaxf(mx, fmaxf(f.x, f.y));
        }
    }
#pragma unroll
    for (int o = 16; o > 0; o >>= 1) mx = fmaxf(mx, __shfl_xor_sync(0xffffffffu, mx, o));

    __shared__ float red[8];
    if ((t & 31) == 0) red[t >> 5] = mx;
    __syncthreads();
    mx = red[0];
#pragma unroll
    for (int i = 1; i < 8; i++) mx = fmaxf(mx, red[i]);

    float sum = 0.0f;
#pragma unroll
    for (int k = 0; k < 2; k++)
#pragma unroll
        for (int j = 0; j < 8; j++) {
            v[k][j] = __expf(v[k][j] - mx);
            sum += v[k][j];
        }
#pragma unroll
    for (int o = 16; o > 0; o >>= 1) sum += __shfl_xor_sync(0xffffffffu, sum, o);
    __syncthreads();
    if ((t & 31) == 0) red[t >> 5] = sum;
    __syncthreads();
    float tot = 0.0f;
#pragma unroll
    for (int i = 0; i < 8; i++) tot += red[i];

    const float inv = 1.0f / tot;
#pragma unroll
    for (int k = 0; k < 2; k++) {
        uint32_t* w = (uint32_t*)&u[k];
#pragma unroll
        for (int j = 0; j < 4; j++) {
            __half2 h = __floats2half2_rn(v[k][2 * j] * inv, v[k][2 * j + 1] * inv);
            w[j] = *(uint32_t*)&h;
        }
        p[t + 256 * k] = u[k];
    }
}

// ---------------------------------------------------------------------------
extern "C" void kernel_launch(void* const* d_in, const int* in_sizes, int n_in,
                              void* d_out, int out_size)
{
    const float* X  = (const float*)d_in[0];
    const float* Wq = (const float*)d_in[1];
    const float* bq = (const float*)d_in[2];
    const float* Wk = (const float*)d_in[3];
    const float* bk = (const float*)d_in[4];
    const float* Wv = (const float*)d_in[5];
    const float* bv = (const float*)d_in[6];
    float* out = (float*)d_out;

    __half *Qh, *Kh, *VTh, *P, *Xh, *Wh;
    cudaGetSymbolAddress((void**)&Qh,  g_Qh);
    cudaGetSymbolAddress((void**)&Kh,  g_Kh);
    cudaGetSymbolAddress((void**)&VTh, g_VTh);
    cudaGetSymbolAddress((void**)&P,   g_P);
    cudaGetSymbolAddress((void**)&Xh,  g_Xh);
    cudaGetSymbolAddress((void**)&Wh,  g_Wh);
    __half* Wqh = Wh;
    __half* Wkh = Wh + (size_t)DIM * DIM;
    __half* Wvh = Wh + (size_t)2 * DIM * DIM;

    cudaFuncSetAttribute(mma_gemm_h<true,  false, true >, cudaFuncAttributeMaxDynamicSharedMemorySize, SMEM_TOTAL);
    cudaFuncSetAttribute(mma_gemm_h<true,  true,  true >, cudaFuncAttributeMaxDynamicSharedMemorySize, SMEM_TOTAL);
    cudaFuncSetAttribute(mma_gemm_h<false, false, true >, cudaFuncAttributeMaxDynamicSharedMemorySize, SMEM_TOTAL);
    cudaFuncSetAttribute(mma_gemm_h<false, false, false>, cudaFuncAttributeMaxDynamicSharedMemorySize, SMEM_TOTAL);

    static cudaStream_t s1 = nullptr, s2 = nullptr;
    static cudaEvent_t evF = nullptr, evK = nullptr, evS0 = nullptr,
                       evV = nullptr, evSm0 = nullptr;
    if (!s1) {
        cudaStreamCreateWithFlags(&s1, cudaStreamNonBlocking);
        cudaStreamCreateWithFlags(&s2, cudaStreamNonBlocking);
        cudaEventCreateWithFlags(&evF,   cudaEventDisableTiming);
        cudaEventCreateWithFlags(&evK,   cudaEventDisableTiming);
        cudaEventCreateWithFlags(&evS0,  cudaEventDisableTiming);
        cudaEventCreateWithFlags(&evV,   cudaEventDisableTiming);
        cudaEventCreateWithFlags(&evSm0, cudaEventDisableTiming);
    }

    const int M0 = 3072;                      // S split point (rows)
    dim3 blk(256);
    dim3 gQK(DIM / BN, SEQ / BM);             // (8, 32)
    dim3 gVT(SEQ / BN, DIM / BM);             // (32, 8)
    dim3 gS0(SEQ / BN, M0 / BM);              // (32, 24) rows 0..3071
    dim3 gS1(SEQ / BN, (SEQ - M0) / BM);      // (32, 8)  rows 3072..4095
    dim3 gO(DIM / BN, SEQ / BM);              // (8, 32)

    // fused fp32->fp16 of all operands
    f2h_all<<<(SEQ * DIM + 3 * DIM * DIM) / 1024, 256>>>(X, Wq, Wk, Wv, Xh, Wh);
    cudaEventRecord(evF, 0);

    // K on s2, concurrent with Q on main
    cudaStreamWaitEvent(s2, evF, 0);
    mma_gemm_h<true, false, true ><<<gQK, blk, SMEM_TOTAL, s2>>>(Xh, Wkh, bk, Kh, DIM, DIM, 1.0f);
    cudaEventRecord(evK, s2);

    mma_gemm_h<true, false, true ><<<gQK, blk, SMEM_TOTAL>>>(Xh, Wqh, bq, Qh, DIM, DIM, 1.0f);

    // S0 = (Q[0:3072] @ K^T) / 32
    cudaStreamWaitEvent(0, evK, 0);
    mma_gemm_h<false, false, true ><<<gS0, blk, SMEM_TOTAL>>>(Qh, Kh, nullptr, P, DIM, SEQ, 0.03125f);
    cudaEventRecord(evS0, 0);

    // concurrent with S1: softmax0 on s1 (memory-bound), VT on s2 (fills S1's tail)
    cudaStreamWaitEvent(s1, evS0, 0);
    softmax4096h<<<M0, 256, 0, s1>>>(P);
    cudaEventRecord(evSm0, s1);

    cudaStreamWaitEvent(s2, evS0, 0);
    mma_gemm_h<true, true, true ><<<gVT, blk, SMEM_TOTAL, s2>>>(Wvh, Xh, bv, VTh, DIM, SEQ, 1.0f);
    cudaEventRecord(evV, s2);

    // S1 = (Q[3072:4096] @ K^T) / 32 (main)
    mma_gemm_h<false, false, true ><<<gS1, blk, SMEM_TOTAL>>>(
        Qh + (size_t)M0 * DIM, Kh, nullptr, P + (size_t)M0 * SEQ, DIM, SEQ, 0.03125f);

    // softmax1 (1024 rows) — the only exposed softmax
    softmax4096h<<<SEQ - M0, 256>>>(P + (size_t)M0 * SEQ);

    // join softmax0 + VT, then out = P @ (VT)^T
    cudaStreamWaitEvent(0, evSm0, 0);
    cudaStreamWaitEvent(0, evV, 0);
    mma_gemm_h<false, false, false><<<gO, blk, SMEM_TOTAL>>>(P, VTh, nullptr, out, SEQ, DIM, 1.0f);
}

// round 16
// speedup vs baseline: 1.0561x; 1.0561x over previous
#include <cuda_runtime.h>
#include <cuda_fp16.h>
#include <cstdint>
#include <math.h>

#define SEQ 4096
#define DIM 1024

// ---------------- static device scratch (no allocation APIs) ----------------
__device__ __half g_Qh [SEQ * DIM];
__device__ __half g_Kh [SEQ * DIM];
__device__ __half g_VTh[SEQ * DIM];               // V transposed: [DIM][SEQ]
__device__ __half g_P  [(size_t)SEQ * SEQ];       // scores -> probs (fp16, in-place)
__device__ __half g_Xh [SEQ * DIM];               // fp16-rounded X
__device__ __half g_Wh [3 * DIM * DIM];           // fp16-rounded Wq,Wk,Wv

// ---------------- helpers ----------------
__device__ __forceinline__ uint32_t smem_u32(const void* p) {
    uint32_t a;
    asm("{ .reg .u64 t; cvta.to.shared.u64 t, %1; cvt.u32.u64 %0, t; }" : "=r"(a) : "l"(p));
    return a;
}
#define CP_COMMIT() asm volatile("cp.async.commit_group;" ::: "memory")
#define CP_WAIT(n)  asm volatile("cp.async.wait_group %0;" :: "n"(n) : "memory")

__device__ __forceinline__ void mma_f16(float* d, const uint32_t* a, const uint32_t* b) {
    asm volatile(
        "mma.sync.aligned.m16n8k16.row.col.f32.f16.f16.f32 "
        "{%0,%1,%2,%3}, {%4,%5,%6,%7}, {%8,%9}, {%0,%1,%2,%3};"
        : "+f"(d[0]), "+f"(d[1]), "+f"(d[2]), "+f"(d[3])
        : "r"(a[0]), "r"(a[1]), "r"(a[2]), "r"(a[3]), "r"(b[0]), "r"(b[1]));
}

#define LDSM_X4(r0, r1, r2, r3, addr) \
    asm volatile("ldmatrix.sync.aligned.m8n8.x4.shared.b16 {%0,%1,%2,%3}, [%4];" \
                 : "=r"(r0), "=r"(r1), "=r"(r2), "=r"(r3) : "r"(addr))

// ---------------- tile geometry (proven config — FROZEN) ----------------
// Block 128x128, BK=64 halves. 8 warps (2m x 4n), warp tile 64x32. 2 CTAs/SM.
static constexpr int BM           = 128;
static constexpr int BN           = 128;
static constexpr int STAGES       = 3;
static constexpr int STRIDE_H     = 72;                     // halves per smem row
static constexpr int STAGE_HALVES = (BM + BN) * STRIDE_H;   // 18432
static constexpr int STAGE_BYTES  = STAGE_HALVES * 2;       // 36864
static constexpr int SMEM_TOTAL   = STAGES * STAGE_BYTES;   // 110592

// ---------------------------------------------------------------------------
// NT GEMM: C[M,N] = alpha * A[M,K] * B[N,K]^T (+ bias), fp16 mma, fp32 accum.
// ldmatrix fragment loads. Grid: (N/BN, M/BM), 256 threads, 2 CTAs/SM.
// ---------------------------------------------------------------------------
template <bool HAS_BIAS, bool BIAS_ROW, bool STORE_HALF>
__global__ __launch_bounds__(256, 2)
void mma_gemm_h(const __half* __restrict__ A, const __half* __restrict__ B,
                const float* __restrict__ bias, void* __restrict__ Cv,
                int Kdim, int ldc, float alpha)
{
    extern __shared__ __half sm[];
    const int tid  = threadIdx.x;
    const int lane = tid & 31;
    const int wid  = tid >> 5;
    const int wm   = wid & 1;          // warp m: 0..1 (64 rows each)
    const int wn   = wid >> 1;         // warp n: 0..3 (32 cols each)
    const int lm   = lane >> 2;        // 0..7
    const int lc   = lane & 3;         // 0..3
    const int by   = blockIdx.y * BM;
    const int bx   = blockIdx.x * BN;

    const uint32_t sbase = smem_u32(sm);
    const __half* Abase = A + (size_t)by * Kdim;
    const __half* Bbase = B + (size_t)bx * Kdim;

    const uint32_t aOff = (uint32_t)(((wm * 64 + (lane & 15)) * STRIDE_H
                                      + (lane >> 4) * 8) * 2);
    const uint32_t bOff = (uint32_t)(((BM + wn * 32 + ((lane >> 4) & 1) * 8 + (lane & 7)) * STRIDE_H
                                      + ((lane >> 3) & 1) * 8) * 2);

    float acc[4][4][4];                // 4 mt x 4 nt x 4 = 64 regs
#pragma unroll
    for (int mt = 0; mt < 4; mt++)
#pragma unroll
        for (int nt = 0; nt < 4; nt++)
#pragma unroll
            for (int q = 0; q < 4; q++) acc[mt][nt][q] = 0.0f;

    const int NK = Kdim >> 6;          // K chunks of 64 halves

    const int ldRow = tid >> 3;        // 0..31
    const int ldC16 = tid & 7;         // 0..7

#define LOAD_STAGE(chunk, stg) do {                                              \
    const int _k0 = (chunk) * 64;                                                \
    const uint32_t _s = sbase + (stg) * STAGE_BYTES;                             \
    _Pragma("unroll")                                                            \
    for (int _i = 0; _i < 4; _i++) {                                             \
        const int _row = _i * 32 + ldRow;                                        \
        const uint32_t _dst = _s + (uint32_t)(_row * STRIDE_H + ldC16 * 8) * 2;  \
        const __half* _g = Abase + (size_t)_row * Kdim + _k0 + ldC16 * 8;        \
        asm volatile("cp.async.cg.shared.global [%0], [%1], 16;"                 \
                     :: "r"(_dst), "l"(_g) : "memory");                          \
    }                                                                            \
    _Pragma("unroll")                                                            \
    for (int _i = 0; _i < 4; _i++) {                                             \
        const int _row = _i * 32 + ldRow;                                        \
        const uint32_t _dst = _s + (uint32_t)((BM + _row) * STRIDE_H + ldC16 * 8) * 2; \
        const __half* _g = Bbase + (size_t)_row * Kdim + _k0 + ldC16 * 8;        \
        asm volatile("cp.async.cg.shared.global [%0], [%1], 16;"                 \
                     :: "r"(_dst), "l"(_g) : "memory");                          \
    }                                                                            \
} while (0)

#pragma unroll
    for (int s = 0; s < STAGES - 1; s++) {
        if (s < NK) LOAD_STAGE(s, s);
        CP_COMMIT();
    }

    for (int c = 0; c < NK; c++) {
        CP_WAIT(STAGES - 2);
        __syncthreads();               // chunk c resident; stage (c-1)%S free

        const uint32_t sstage = sbase + (c % STAGES) * STAGE_BYTES;
        const uint32_t aAddr = sstage + aOff;
        const uint32_t bAddr = sstage + bOff;

#pragma unroll
        for (int ks = 0; ks < 4; ks++) {       // 4 x k16 slices
            uint32_t afr[4][4], bfr[4][2];
#pragma unroll
            for (int mt = 0; mt < 4; mt++)
                LDSM_X4(afr[mt][0], afr[mt][1], afr[mt][2], afr[mt][3],
                        aAddr + (uint32_t)(mt * 16 * STRIDE_H * 2 + ks * 32));
#pragma unroll
            for (int nt2 = 0; nt2 < 2; nt2++)
                LDSM_X4(bfr[2 * nt2][0], bfr[2 * nt2][1],
                        bfr[2 * nt2 + 1][0], bfr[2 * nt2 + 1][1],
                        bAddr + (uint32_t)(nt2 * 16 * STRIDE_H * 2 + ks * 32));
#pragma unroll
            for (int mt = 0; mt < 4; mt++)
#pragma unroll
                for (int nt = 0; nt < 4; nt++)
                    mma_f16(acc[mt][nt], afr[mt], bfr[nt]);
        }

        const int nc = c + STAGES - 1;
        if (nc < NK) LOAD_STAGE(nc, nc % STAGES);
        CP_COMMIT();
    }
#undef LOAD_STAGE

    // ---- epilogue ----
#pragma unroll
    for (int mt = 0; mt < 4; mt++) {
        const int row0 = by + wm * 64 + mt * 16 + lm;   // and row0+8
        float brow0 = 0.0f, brow1 = 0.0f;
        if (HAS_BIAS && BIAS_ROW) { brow0 = bias[row0]; brow1 = bias[row0 + 8]; }
#pragma unroll
        for (int nt = 0; nt < 4; nt++) {
            const int col = bx + wn * 32 + nt * 8 + lc * 2;
            float v0 = acc[mt][nt][0] * alpha;
            float v1 = acc[mt][nt][1] * alpha;
            float v2 = acc[mt][nt][2] * alpha;
            float v3 = acc[mt][nt][3] * alpha;
            if (HAS_BIAS) {
                if (BIAS_ROW) { v0 += brow0; v1 += brow0; v2 += brow1; v3 += brow1; }
                else {
                    const float bc0 = bias[col], bc1 = bias[col + 1];
                    v0 += bc0; v1 += bc1; v2 += bc0; v3 += bc1;
                }
            }
            if (STORE_HALF) {
                __half* C = (__half*)Cv;
                *(__half2*)(C + (size_t)row0 * ldc + col)       = __floats2half2_rn(v0, v1);
                *(__half2*)(C + (size_t)(row0 + 8) * ldc + col) = __floats2half2_rn(v2, v3);
            } else {
                float* C = (float*)Cv;
                *(float2*)(C + (size_t)row0 * ldc + col)       = make_float2(v0, v1);
                *(float2*)(C + (size_t)(row0 + 8) * ldc + col) = make_float2(v2, v3);
            }
        }
    }
}

// ---------------------------------------------------------------------------
// Single fused fp32 -> fp16 pre-pass over X, Wq, Wk, Wv (one launch).
// ---------------------------------------------------------------------------
__global__ void f2h_all(const float* __restrict__ X,
                        const float* __restrict__ Wq,
                        const float* __restrict__ Wk,
                        const float* __restrict__ Wv,
                        __half* __restrict__ Xh, __half* __restrict__ Wh)
{
    const int NX = SEQ * DIM;
    const int NW = DIM * DIM;
    int i = (blockIdx.x * blockDim.x + threadIdx.x) * 4;

    const float* src;
    __half* dst;
    int off;
    if (i < NX)               { src = X;  dst = Xh;          off = i; }
    else if (i < NX + NW)     { src = Wq; dst = Wh;          off = i - NX; }
    else if (i < NX + 2 * NW) { src = Wk; dst = Wh + NW;     off = i - NX - NW; }
    else                      { src = Wv; dst = Wh + 2 * NW; off = i - NX - 2 * NW; }

    float4 v = *(const float4*)(src + off);
    __half2 h0 = __floats2half2_rn(v.x, v.y);
    __half2 h1 = __floats2half2_rn(v.z, v.w);
    uint2 u;
    u.x = *(uint32_t*)&h0;
    u.y = *(uint32_t*)&h1;
    *(uint2*)(dst + off) = u;
}

// ---------------------------------------------------------------------------
// In-place row softmax on fp16 scores (4096-wide rows, one block per row).
// ---------------------------------------------------------------------------
__global__ void softmax4096h(__half* __restrict__ P) {
    const int row = blockIdx.x;
    uint4* p = (uint4*)(P + (size_t)row * SEQ);   // 8 halves per uint4
    const int t = threadIdx.x;

    uint4 u[2];
    float v[2][8];
    float mx = -1e30f;
#pragma unroll
    for (int k = 0; k < 2; k++) {
        u[k] = p[t + 256 * k];
        const uint32_t* w = (const uint32_t*)&u[k];
#pragma unroll
        for (int j = 0; j < 4; j++) {
            float2 f = __half22float2(*(const __half2*)&w[j]);
            v[k][2 * j]     = f.x;
            v[k][2 * j + 1] = f.y;
            mx = fmaxf(mx, fmaxf(f.x, f.y));
        }
    }
#pragma unroll
    for (int o = 16; o > 0; o >>= 1) mx = fmaxf(mx, __shfl_xor_sync(0xffffffffu, mx, o));

    __shared__ float red[8];
    if ((t & 31) == 0) red[t >> 5] = mx;
    __syncthreads();
    mx = red[0];
#pragma unroll
    for (int i = 1; i < 8; i++) mx = fmaxf(mx, red[i]);

    float sum = 0.0f;
#pragma unroll
    for (int k = 0; k < 2; k++)
#pragma unroll
        for (int j = 0; j < 8; j++) {
            v[k][j] = __expf(v[k][j] - mx);
            sum += v[k][j];
        }
#pragma unroll
    for (int o = 16; o > 0; o >>= 1) sum += __shfl_xor_sync(0xffffffffu, sum, o);
    __syncthreads();
    if ((t & 31) == 0) red[t >> 5] = sum;
    __syncthreads();
    float tot = 0.0f;
#pragma unroll
    for (int i = 0; i < 8; i++) tot += red[i];

    const float inv = 1.0f / tot;
#pragma unroll
    for (int k = 0; k < 2; k++) {
        uint32_t* w = (uint32_t*)&u[k];
#pragma unroll
        for (int j = 0; j < 4; j++) {
            __half2 h = __floats2half2_rn(v[k][2 * j] * inv, v[k][2 * j + 1] * inv);
            w[j] = *(uint32_t*)&h;
        }
        p[t + 256 * k] = u[k];
    }
}

// ---------------------------------------------------------------------------
extern "C" void kernel_launch(void* const* d_in, const int* in_sizes, int n_in,
                              void* d_out, int out_size)
{
    const float* X  = (const float*)d_in[0];
    const float* Wq = (const float*)d_in[1];
    const float* bq = (const float*)d_in[2];
    const float* Wk = (const float*)d_in[3];
    const float* bk = (const float*)d_in[4];
    const float* Wv = (const float*)d_in[5];
    const float* bv = (const float*)d_in[6];
    float* out = (float*)d_out;

    __half *Qh, *Kh, *VTh, *P, *Xh, *Wh;
    cudaGetSymbolAddress((void**)&Qh,  g_Qh);
    cudaGetSymbolAddress((void**)&Kh,  g_Kh);
    cudaGetSymbolAddress((void**)&VTh, g_VTh);
    cudaGetSymbolAddress((void**)&P,   g_P);
    cudaGetSymbolAddress((void**)&Xh,  g_Xh);
    cudaGetSymbolAddress((void**)&Wh,  g_Wh);
    __half* Wqh = Wh;
    __half* Wkh = Wh + (size_t)DIM * DIM;
    __half* Wvh = Wh + (size_t)2 * DIM * DIM;

    cudaFuncSetAttribute(mma_gemm_h<true,  false, true >, cudaFuncAttributeMaxDynamicSharedMemorySize, SMEM_TOTAL);
    cudaFuncSetAttribute(mma_gemm_h<true,  true,  true >, cudaFuncAttributeMaxDynamicSharedMemorySize, SMEM_TOTAL);
    cudaFuncSetAttribute(mma_gemm_h<false, false, true >, cudaFuncAttributeMaxDynamicSharedMemorySize, SMEM_TOTAL);
    cudaFuncSetAttribute(mma_gemm_h<false, false, false>, cudaFuncAttributeMaxDynamicSharedMemorySize, SMEM_TOTAL);

    // one side stream + two events: the ONLY overlap that measurably pays
    // (VT projection hidden under softmax). Q/K concurrency removed — wave
    // quantization makes it a proven zero (512 CTAs = 2 waves either way).
    static cudaStream_t s1 = nullptr;
    static cudaEvent_t evS = nullptr, evV = nullptr;
    if (!s1) {
        cudaStreamCreateWithFlags(&s1, cudaStreamNonBlocking);
        cudaEventCreateWithFlags(&evS, cudaEventDisableTiming);
        cudaEventCreateWithFlags(&evV, cudaEventDisableTiming);
    }

    dim3 blk(256);
    dim3 gQK(DIM / BN, SEQ / BM);            // (8, 32)
    dim3 gVT(SEQ / BN, DIM / BM);            // (32, 8)
    dim3 gS(SEQ / BN, SEQ / BM);             // (32, 32)
    dim3 gO(DIM / BN, SEQ / BM);             // (8, 32)

    // fused fp32->fp16 of all operands (one launch)
    f2h_all<<<(SEQ * DIM + 3 * DIM * DIM) / 1024, 256>>>(X, Wq, Wk, Wv, Xh, Wh);

    // Q, K projections (serial — wave-equivalent to concurrent, fewer joins)
    mma_gemm_h<true, false, true ><<<gQK, blk, SMEM_TOTAL>>>(Xh, Wqh, bq, Qh, DIM, DIM, 1.0f);
    mma_gemm_h<true, false, true ><<<gQK, blk, SMEM_TOTAL>>>(Xh, Wkh, bk, Kh, DIM, DIM, 1.0f);

    // S = (Q @ K^T) / 32, stored fp16 directly
    mma_gemm_h<false, false, true ><<<gS, blk, SMEM_TOTAL>>>(Qh, Kh, nullptr, P, DIM, SEQ, 0.03125f);

    // fork: VT projection on side stream, concurrent with softmax (the one
    // overlap that hides tensor work under memory-bound work)
    cudaEventRecord(evS, 0);
    cudaStreamWaitEvent(s1, evS, 0);
    mma_gemm_h<true, true, true ><<<gVT, blk, SMEM_TOTAL, s1>>>(Wvh, Xh, bv, VTh, DIM, SEQ, 1.0f);
    cudaEventRecord(evV, s1);

    softmax4096h<<<SEQ, 256>>>(P);           // in-place, main stream

    // join VT, then out = P @ (VT)^T
    cudaStreamWaitEvent(0, evV, 0);
    mma_gemm_h<false, false, false><<<gO, blk, SMEM_TOTAL>>>(P, VTh, nullptr, out, SEQ, DIM, 1.0f);
}

// round 17
// speedup vs baseline: 1.0672x; 1.0105x over previous
#include <cuda_runtime.h>
#include <cuda_fp16.h>
#include <cstdint>
#include <math.h>

#define SEQ 4096
#define DIM 1024

// ---------------- static device scratch (no allocation APIs) ----------------
__device__ __half g_Qh [SEQ * DIM];
__device__ __half g_Kh [SEQ * DIM];
__device__ __half g_VTh[SEQ * DIM];               // V transposed: [DIM][SEQ]
__device__ __half g_P  [(size_t)SEQ * SEQ];       // scores -> probs (fp16, in-place)
__device__ __half g_Xh [SEQ * DIM];               // fp16-rounded X
__device__ __half g_Wh [3 * DIM * DIM];           // fp16-rounded Wq,Wk,Wv

// ---------------- helpers ----------------
__device__ __forceinline__ uint32_t smem_u32(const void* p) {
    uint32_t a;
    asm("{ .reg .u64 t; cvta.to.shared.u64 t, %1; cvt.u32.u64 %0, t; }" : "=r"(a) : "l"(p));
    return a;
}
#define CP_COMMIT() asm volatile("cp.async.commit_group;" ::: "memory")
#define CP_WAIT(n)  asm volatile("cp.async.wait_group %0;" :: "n"(n) : "memory")

__device__ __forceinline__ void mma_f16(float* d, const uint32_t* a, const uint32_t* b) {
    asm volatile(
        "mma.sync.aligned.m16n8k16.row.col.f32.f16.f16.f32 "
        "{%0,%1,%2,%3}, {%4,%5,%6,%7}, {%8,%9}, {%0,%1,%2,%3};"
        : "+f"(d[0]), "+f"(d[1]), "+f"(d[2]), "+f"(d[3])
        : "r"(a[0]), "r"(a[1]), "r"(a[2]), "r"(a[3]), "r"(b[0]), "r"(b[1]));
}

#define LDSM_X4(r0, r1, r2, r3, addr) \
    asm volatile("ldmatrix.sync.aligned.m8n8.x4.shared.b16 {%0,%1,%2,%3}, [%4];" \
                 : "=r"(r0), "=r"(r1), "=r"(r2), "=r"(r3) : "r"(addr))

// ---------------- tile geometry (proven config — FROZEN) ----------------
// Block 128x128, BK=64 halves. 8 warps (2m x 4n), warp tile 64x32. 2 CTAs/SM.
static constexpr int BM           = 128;
static constexpr int BN           = 128;
static constexpr int STAGES       = 3;
static constexpr int STRIDE_H     = 72;                     // halves per smem row
static constexpr int STAGE_HALVES = (BM + BN) * STRIDE_H;   // 18432
static constexpr int STAGE_BYTES  = STAGE_HALVES * 2;       // 36864
static constexpr int SMEM_TOTAL   = STAGES * STAGE_BYTES;   // 110592

// ---------------------------------------------------------------------------
// NT GEMM: C[M,N] = alpha * A[M,K] * B[N,K]^T (+ bias), fp16 mma, fp32 accum.
// ldmatrix fragment loads. Grid: (N/BN, M/BM), 256 threads, 2 CTAs/SM.
// ---------------------------------------------------------------------------
template <bool HAS_BIAS, bool BIAS_ROW, bool STORE_HALF>
__global__ __launch_bounds__(256, 2)
void mma_gemm_h(const __half* __restrict__ A, const __half* __restrict__ B,
                const float* __restrict__ bias, void* __restrict__ Cv,
                int Kdim, int ldc, float alpha)
{
    extern __shared__ __half sm[];
    const int tid  = threadIdx.x;
    const int lane = tid & 31;
    const int wid  = tid >> 5;
    const int wm   = wid & 1;          // warp m: 0..1 (64 rows each)
    const int wn   = wid >> 1;         // warp n: 0..3 (32 cols each)
    const int lm   = lane >> 2;        // 0..7
    const int lc   = lane & 3;         // 0..3
    const int by   = blockIdx.y * BM;
    const int bx   = blockIdx.x * BN;

    const uint32_t sbase = smem_u32(sm);
    const __half* Abase = A + (size_t)by * Kdim;
    const __half* Bbase = B + (size_t)bx * Kdim;

    const uint32_t aOff = (uint32_t)(((wm * 64 + (lane & 15)) * STRIDE_H
                                      + (lane >> 4) * 8) * 2);
    const uint32_t bOff = (uint32_t)(((BM + wn * 32 + ((lane >> 4) & 1) * 8 + (lane & 7)) * STRIDE_H
                                      + ((lane >> 3) & 1) * 8) * 2);

    float acc[4][4][4];                // 4 mt x 4 nt x 4 = 64 regs
#pragma unroll
    for (int mt = 0; mt < 4; mt++)
#pragma unroll
        for (int nt = 0; nt < 4; nt++)
#pragma unroll
            for (int q = 0; q < 4; q++) acc[mt][nt][q] = 0.0f;

    const int NK = Kdim >> 6;          // K chunks of 64 halves

    const int ldRow = tid >> 3;        // 0..31
    const int ldC16 = tid & 7;         // 0..7

#define LOAD_STAGE(chunk, stg) do {                                              \
    const int _k0 = (chunk) * 64;                                                \
    const uint32_t _s = sbase + (stg) * STAGE_BYTES;                             \
    _Pragma("unroll")                                                            \
    for (int _i = 0; _i < 4; _i++) {                                             \
        const int _row = _i * 32 + ldRow;                                        \
        const uint32_t _dst = _s + (uint32_t)(_row * STRIDE_H + ldC16 * 8) * 2;  \
        const __half* _g = Abase + (size_t)_row * Kdim + _k0 + ldC16 * 8;        \
        asm volatile("cp.async.cg.shared.global [%0], [%1], 16;"                 \
                     :: "r"(_dst), "l"(_g) : "memory");                          \
    }                                                                            \
    _Pragma("unroll")                                                            \
    for (int _i = 0; _i < 4; _i++) {                                             \
        const int _row = _i * 32 + ldRow;                                        \
        const uint32_t _dst = _s + (uint32_t)((BM + _row) * STRIDE_H + ldC16 * 8) * 2; \
        const __half* _g = Bbase + (size_t)_row * Kdim + _k0 + ldC16 * 8;        \
        asm volatile("cp.async.cg.shared.global [%0], [%1], 16;"                 \
                     :: "r"(_dst), "l"(_g) : "memory");                          \
    }                                                                            \
} while (0)

#pragma unroll
    for (int s = 0; s < STAGES - 1; s++) {
        if (s < NK) LOAD_STAGE(s, s);
        CP_COMMIT();
    }

    for (int c = 0; c < NK; c++) {
        CP_WAIT(STAGES - 2);
        __syncthreads();               // chunk c resident; stage (c-1)%S free

        const uint32_t sstage = sbase + (c % STAGES) * STAGE_BYTES;
        const uint32_t aAddr = sstage + aOff;
        const uint32_t bAddr = sstage + bOff;

#pragma unroll
        for (int ks = 0; ks < 4; ks++) {       // 4 x k16 slices
            uint32_t afr[4][4], bfr[4][2];
#pragma unroll
            for (int mt = 0; mt < 4; mt++)
                LDSM_X4(afr[mt][0], afr[mt][1], afr[mt][2], afr[mt][3],
                        aAddr + (uint32_t)(mt * 16 * STRIDE_H * 2 + ks * 32));
#pragma unroll
            for (int nt2 = 0; nt2 < 2; nt2++)
                LDSM_X4(bfr[2 * nt2][0], bfr[2 * nt2][1],
                        bfr[2 * nt2 + 1][0], bfr[2 * nt2 + 1][1],
                        bAddr + (uint32_t)(nt2 * 16 * STRIDE_H * 2 + ks * 32));
#pragma unroll
            for (int mt = 0; mt < 4; mt++)
#pragma unroll
                for (int nt = 0; nt < 4; nt++)
                    mma_f16(acc[mt][nt], afr[mt], bfr[nt]);
        }

        const int nc = c + STAGES - 1;
        if (nc < NK) LOAD_STAGE(nc, nc % STAGES);
        CP_COMMIT();
    }
#undef LOAD_STAGE

    // ---- epilogue ----
#pragma unroll
    for (int mt = 0; mt < 4; mt++) {
        const int row0 = by + wm * 64 + mt * 16 + lm;   // and row0+8
        float brow0 = 0.0f, brow1 = 0.0f;
        if (HAS_BIAS && BIAS_ROW) { brow0 = bias[row0]; brow1 = bias[row0 + 8]; }
#pragma unroll
        for (int nt = 0; nt < 4; nt++) {
            const int col = bx + wn * 32 + nt * 8 + lc * 2;
            float v0 = acc[mt][nt][0] * alpha;
            float v1 = acc[mt][nt][1] * alpha;
            float v2 = acc[mt][nt][2] * alpha;
            float v3 = acc[mt][nt][3] * alpha;
            if (HAS_BIAS) {
                if (BIAS_ROW) { v0 += brow0; v1 += brow0; v2 += brow1; v3 += brow1; }
                else {
                    const float bc0 = bias[col], bc1 = bias[col + 1];
                    v0 += bc0; v1 += bc1; v2 += bc0; v3 += bc1;
                }
            }
            if (STORE_HALF) {
                __half* C = (__half*)Cv;
                *(__half2*)(C + (size_t)row0 * ldc + col)       = __floats2half2_rn(v0, v1);
                *(__half2*)(C + (size_t)(row0 + 8) * ldc + col) = __floats2half2_rn(v2, v3);
            } else {
                float* C = (float*)Cv;
                *(float2*)(C + (size_t)row0 * ldc + col)       = make_float2(v0, v1);
                *(float2*)(C + (size_t)(row0 + 8) * ldc + col) = make_float2(v2, v3);
            }
        }
    }
}

// ---------------------------------------------------------------------------
// Fused fp32 -> fp16 pre-pass, 4x ILP: each thread converts 16 consecutive
// floats (4 independent float4 loads in flight). Segments are 16-aligned.
// ---------------------------------------------------------------------------
__global__ void f2h_all(const float* __restrict__ X,
                        const float* __restrict__ Wq,
                        const float* __restrict__ Wk,
                        const float* __restrict__ Wv,
                        __half* __restrict__ Xh, __half* __restrict__ Wh)
{
    const int NX = SEQ * DIM;          // 4M
    const int NW = DIM * DIM;          // 1M
    int i = (blockIdx.x * blockDim.x + threadIdx.x) * 16;

    const float* src;
    __half* dst;
    int off;
    if (i < NX)               { src = X;  dst = Xh;          off = i; }
    else if (i < NX + NW)     { src = Wq; dst = Wh;          off = i - NX; }
    else if (i < NX + 2 * NW) { src = Wk; dst = Wh + NW;     off = i - NX - NW; }
    else                      { src = Wv; dst = Wh + 2 * NW; off = i - NX - 2 * NW; }

    float4 v0 = *(const float4*)(src + off);
    float4 v1 = *(const float4*)(src + off + 4);
    float4 v2 = *(const float4*)(src + off + 8);
    float4 v3 = *(const float4*)(src + off + 12);

    uint4 o0, o1;
    __half2 h;
    h = __floats2half2_rn(v0.x, v0.y); o0.x = *(uint32_t*)&h;
    h = __floats2half2_rn(v0.z, v0.w); o0.y = *(uint32_t*)&h;
    h = __floats2half2_rn(v1.x, v1.y); o0.z = *(uint32_t*)&h;
    h = __floats2half2_rn(v1.z, v1.w); o0.w = *(uint32_t*)&h;
    h = __floats2half2_rn(v2.x, v2.y); o1.x = *(uint32_t*)&h;
    h = __floats2half2_rn(v2.z, v2.w); o1.y = *(uint32_t*)&h;
    h = __floats2half2_rn(v3.x, v3.y); o1.z = *(uint32_t*)&h;
    h = __floats2half2_rn(v3.z, v3.w); o1.w = *(uint32_t*)&h;

    *(uint4*)(dst + off)     = o0;
    *(uint4*)(dst + off + 8) = o1;
}

// ---------------------------------------------------------------------------
// Warp-per-row softmax on fp16 scores, in place. One warp owns one 4096-wide
// row (16 uint4 per lane, MLP=16). Shuffle-only reductions, no smem/barriers.
// Grid: SEQ/8 blocks of 256 threads (8 warps).
// ---------------------------------------------------------------------------
__global__ void softmax4096w(__half* __restrict__ P) {
    const int lane = threadIdx.x & 31;
    const int row  = blockIdx.x * 8 + (threadIdx.x >> 5);
    uint4* p = (uint4*)(P + (size_t)row * SEQ);

    uint4 u[16];
#pragma unroll
    for (int i = 0; i < 16; i++) u[i] = p[lane + 32 * i];

    // ---- max (exact in fp16) ----
    __half2 m2 = *(const __half2*)&u[0].x;
#pragma unroll
    for (int i = 0; i < 16; i++) {
        const uint32_t* w = (const uint32_t*)&u[i];
#pragma unroll
        for (int j = 0; j < 4; j++) m2 = __hmax2(m2, *(const __half2*)&w[j]);
    }
    float mx = fmaxf(__low2float(m2), __high2float(m2));
#pragma unroll
    for (int o = 16; o > 0; o >>= 1) mx = fmaxf(mx, __shfl_xor_sync(0xffffffffu, mx, o));

    // ---- exp + sum (fp32 math, store exp back as fp16) ----
    float sum = 0.0f;
#pragma unroll
    for (int i = 0; i < 16; i++) {
        uint32_t* w = (uint32_t*)&u[i];
#pragma unroll
        for (int j = 0; j < 4; j++) {
            float2 f = __half22float2(*(const __half2*)&w[j]);
            float e0 = __expf(f.x - mx);
            float e1 = __expf(f.y - mx);
            sum += e0 + e1;
            __half2 h = __floats2half2_rn(e0, e1);
            w[j] = *(uint32_t*)&h;
        }
    }
#pragma unroll
    for (int o = 16; o > 0; o >>= 1) sum += __shfl_xor_sync(0xffffffffu, sum, o);

    // ---- scale + store ----
    const float inv = 1.0f / sum;
#pragma unroll
    for (int i = 0; i < 16; i++) {
        uint32_t* w = (uint32_t*)&u[i];
#pragma unroll
        for (int j = 0; j < 4; j++) {
            float2 f = __half22float2(*(const __half2*)&w[j]);
            __half2 h = __floats2half2_rn(f.x * inv, f.y * inv);
            w[j] = *(uint32_t*)&h;
        }
        p[lane + 32 * i] = u[i];
    }
}

// ---------------------------------------------------------------------------
extern "C" void kernel_launch(void* const* d_in, const int* in_sizes, int n_in,
                              void* d_out, int out_size)
{
    const float* X  = (const float*)d_in[0];
    const float* Wq = (const float*)d_in[1];
    const float* bq = (const float*)d_in[2];
    const float* Wk = (const float*)d_in[3];
    const float* bk = (const float*)d_in[4];
    const float* Wv = (const float*)d_in[5];
    const float* bv = (const float*)d_in[6];
    float* out = (float*)d_out;

    __half *Qh, *Kh, *VTh, *P, *Xh, *Wh;
    cudaGetSymbolAddress((void**)&Qh,  g_Qh);
    cudaGetSymbolAddress((void**)&Kh,  g_Kh);
    cudaGetSymbolAddress((void**)&VTh, g_VTh);
    cudaGetSymbolAddress((void**)&P,   g_P);
    cudaGetSymbolAddress((void**)&Xh,  g_Xh);
    cudaGetSymbolAddress((void**)&Wh,  g_Wh);
    __half* Wqh = Wh;
    __half* Wkh = Wh + (size_t)DIM * DIM;
    __half* Wvh = Wh + (size_t)2 * DIM * DIM;

    cudaFuncSetAttribute(mma_gemm_h<true,  false, true >, cudaFuncAttributeMaxDynamicSharedMemorySize, SMEM_TOTAL);
    cudaFuncSetAttribute(mma_gemm_h<true,  true,  true >, cudaFuncAttributeMaxDynamicSharedMemorySize, SMEM_TOTAL);
    cudaFuncSetAttribute(mma_gemm_h<false, false, true >, cudaFuncAttributeMaxDynamicSharedMemorySize, SMEM_TOTAL);
    cudaFuncSetAttribute(mma_gemm_h<false, false, false>, cudaFuncAttributeMaxDynamicSharedMemorySize, SMEM_TOTAL);

    // R12 topology (measured best): K forked beside Q, VT forked beside softmax
    static cudaStream_t s1 = nullptr;
    static cudaEvent_t evF = nullptr, evK = nullptr, evS = nullptr, evV = nullptr;
    if (!s1) {
        cudaStreamCreateWithFlags(&s1, cudaStreamNonBlocking);
        cudaEventCreateWithFlags(&evF, cudaEventDisableTiming);
        cudaEventCreateWithFlags(&evK, cudaEventDisableTiming);
        cudaEventCreateWithFlags(&evS, cudaEventDisableTiming);
        cudaEventCreateWithFlags(&evV, cudaEventDisableTiming);
    }

    dim3 blk(256);
    dim3 gQK(DIM / BN, SEQ / BM);            // (8, 32)
    dim3 gVT(SEQ / BN, DIM / BM);            // (32, 8)
    dim3 gS(SEQ / BN, SEQ / BM);             // (32, 32)
    dim3 gO(DIM / BN, SEQ / BM);             // (8, 32)

    // fused fp32->fp16 of all operands (one launch, 4x ILP)
    f2h_all<<<(SEQ * DIM + 3 * DIM * DIM) / (256 * 16), 256>>>(X, Wq, Wk, Wv, Xh, Wh);
    cudaEventRecord(evF, 0);

    // fork: K projection on side stream, concurrent with Q projection
    cudaStreamWaitEvent(s1, evF, 0);
    mma_gemm_h<true, false, true ><<<gQK, blk, SMEM_TOTAL, s1>>>(Xh, Wkh, bk, Kh, DIM, DIM, 1.0f);
    cudaEventRecord(evK, s1);

    mma_gemm_h<true, false, true ><<<gQK, blk, SMEM_TOTAL>>>(Xh, Wqh, bq, Qh, DIM, DIM, 1.0f);

    // join K, then S = (Q @ K^T) / 32 stored as fp16 directly
    cudaStreamWaitEvent(0, evK, 0);
    mma_gemm_h<false, false, true ><<<gS, blk, SMEM_TOTAL>>>(Qh, Kh, nullptr, P, DIM, SEQ, 0.03125f);

    // fork: VT projection on side stream, concurrent with softmax
    cudaEventRecord(evS, 0);
    cudaStreamWaitEvent(s1, evS, 0);
    mma_gemm_h<true, true, true ><<<gVT, blk, SMEM_TOTAL, s1>>>(Wvh, Xh, bv, VTh, DIM, SEQ, 1.0f);
    cudaEventRecord(evV, s1);

    softmax4096w<<<SEQ / 8, 256>>>(P);       // warp-per-row, in place

    // join VT, then out = P @ (VT)^T
    cudaStreamWaitEvent(0, evV, 0);
    mma_gemm_h<false, false, false><<<gO, blk, SMEM_TOTAL>>>(P, VTh, nullptr, out, SEQ, DIM, 1.0f);
}